// round 3
// baseline (speedup 1.0000x reference)
#include <cuda_runtime.h>
#include <cstdint>

#define INV_SQRT2 0.7071067811865476f

// x: (B=64, S=4096, F=256) fp32 contiguous -> out (B, 2048, 512):
//   out[b,s2,2f]   = (x[b,2s2,f] + x[b,2s2+1,f]) * INV_SQRT2
//   out[b,s2,2f+1] = (x[b,2s2,f] - x[b,2s2+1,f]) * INV_SQRT2
//
// Work unit ("chunk") j of pair p: produces output float4 chunks via the
// store-contiguous mapping of R2. Persistent grid-stride kernel, unroll 4:
// 16 independent streaming loads issued up front per iteration (deep MLP),
// then compute + 8 contiguous STG.128.CS.

struct WorkItem {
    float2 a0, b0, a1, b1;
};

__device__ __forceinline__ void haar_body(const float2* __restrict__ x,
                                          float4* __restrict__ out,
                                          int tid,
                                          const WorkItem& w)
{
    int p = tid >> 6;
    int j = tid & 63;

    float4 o0, o1;
    o0.x = (w.a0.x + w.b0.x) * INV_SQRT2;
    o0.y = (w.a0.x - w.b0.x) * INV_SQRT2;
    o0.z = (w.a0.y + w.b0.y) * INV_SQRT2;
    o0.w = (w.a0.y - w.b0.y) * INV_SQRT2;
    o1.x = (w.a1.x + w.b1.x) * INV_SQRT2;
    o1.y = (w.a1.x - w.b1.x) * INV_SQRT2;
    o1.z = (w.a1.y + w.b1.y) * INV_SQRT2;
    o1.w = (w.a1.y - w.b1.y) * INV_SQRT2;

    size_t ob = (size_t)p * 128 + j;
    __stcs(out + ob,      o0);
    __stcs(out + ob + 64, o1);
}

__device__ __forceinline__ WorkItem haar_load(const float2* __restrict__ x, int tid)
{
    int p = tid >> 6;
    int j = tid & 63;
    size_t xb = (size_t)p * 256;
    WorkItem w;
    w.a0 = __ldcs(x + xb + j);
    w.b0 = __ldcs(x + xb + 128 + j);
    w.a1 = __ldcs(x + xb + 64 + j);
    w.b1 = __ldcs(x + xb + 192 + j);
    return w;
}

__global__ void __launch_bounds__(256) haar_kernel(const float2* __restrict__ x,
                                                   float4* __restrict__ out,
                                                   int total_threads)
{
    const int stride = gridDim.x * blockDim.x;
    int tid = blockIdx.x * blockDim.x + threadIdx.x;

    // Main unrolled loop: 4 work items, 16 loads batched before any store.
    for (; tid + 3 * stride < total_threads; tid += 4 * stride) {
        WorkItem w0 = haar_load(x, tid);
        WorkItem w1 = haar_load(x, tid + stride);
        WorkItem w2 = haar_load(x, tid + 2 * stride);
        WorkItem w3 = haar_load(x, tid + 3 * stride);
        haar_body(x, out, tid,              w0);
        haar_body(x, out, tid + stride,     w1);
        haar_body(x, out, tid + 2 * stride, w2);
        haar_body(x, out, tid + 3 * stride, w3);
    }
    // Tail
    for (; tid < total_threads; tid += stride) {
        WorkItem w = haar_load(x, tid);
        haar_body(x, out, tid, w);
    }
}

extern "C" void kernel_launch(void* const* d_in, const int* in_sizes, int n_in,
                              void* d_out, int out_size)
{
    const float2* x = (const float2*)d_in[0];
    float4* out = (float4*)d_out;

    int total_threads = in_sizes[0] / 8;   // 8 floats consumed per work item

    // Persistent: one wave. 148 SMs x 8 blocks of 256 threads (occ 8, 64 warps/SM).
    int blocks = 148 * 8;
    haar_kernel<<<blocks, 256>>>(x, out, total_threads);
}

// round 4
// speedup vs baseline: 1.0550x; 1.0550x over previous
#include <cuda_runtime.h>
#include <cstdint>

#define INV_SQRT2 0.7071067811865476f

// x: (B=64, S=4096, F=256) fp32 contiguous -> out (B, 2048, 512):
//   out[b,s2,2f]   = (x[b,2s2,f] + x[b,2s2+1,f]) * INV_SQRT2
//   out[b,s2,2f+1] = (x[b,2s2,f] - x[b,2s2+1,f]) * INV_SQRT2
//
// R2 store-contiguous mapping, unroll x2 over two distant halves of the
// problem (independent memory streams, MLP=8/thread, regs ~40 -> high occ).
// Loads use ld.global.lu (last-use: evict-first in L2, data is read-once),
// stores use st.global.cs.

__device__ __forceinline__ void haar_item(const float2* __restrict__ x,
                                          float4* __restrict__ out,
                                          int tid)
{
    int p = tid >> 6;        // pair index
    int j = tid & 63;        // chunk-within-pair

    size_t xb = (size_t)p * 256;
    float2 a0 = __ldlu(x + xb + j);
    float2 b0 = __ldlu(x + xb + 128 + j);
    float2 a1 = __ldlu(x + xb + 64 + j);
    float2 b1 = __ldlu(x + xb + 192 + j);

    float4 o0, o1;
    o0.x = (a0.x + b0.x) * INV_SQRT2;
    o0.y = (a0.x - b0.x) * INV_SQRT2;
    o0.z = (a0.y + b0.y) * INV_SQRT2;
    o0.w = (a0.y - b0.y) * INV_SQRT2;
    o1.x = (a1.x + b1.x) * INV_SQRT2;
    o1.y = (a1.x - b1.x) * INV_SQRT2;
    o1.z = (a1.y + b1.y) * INV_SQRT2;
    o1.w = (a1.y - b1.y) * INV_SQRT2;

    size_t ob = (size_t)p * 128 + j;
    __stcs(out + ob,      o0);
    __stcs(out + ob + 64, o1);
}

__global__ void __launch_bounds__(256) haar_kernel(const float2* __restrict__ x,
                                                   float4* __restrict__ out,
                                                   int half_threads)
{
    int tid = blockIdx.x * blockDim.x + threadIdx.x;
    if (tid >= half_threads) return;

    // Two independent streams half the tensor apart.
    haar_item(x, out, tid);
    haar_item(x, out, tid + half_threads);
}

extern "C" void kernel_launch(void* const* d_in, const int* in_sizes, int n_in,
                              void* d_out, int out_size)
{
    const float2* x = (const float2*)d_in[0];
    float4* out = (float4*)d_out;

    int total_threads = in_sizes[0] / 8;   // 8 input floats per work item
    int half_threads = total_threads / 2;  // each thread does 2 items

    int threads = 256;
    int blocks = (half_threads + threads - 1) / threads;
    haar_kernel<<<blocks, threads>>>(x, out, half_threads);
}